// round 2
// baseline (speedup 1.0000x reference)
#include <cuda_runtime.h>
#include <cstdint>

// Problem constants
#define D      150       // true hidden dim
#define Dp     160       // padded hidden dim
#define NT     25600     // Dp*Dp (flattened (i,j))
#define BZ     256       // B*N = 2*128
#define DIN    1024
#define NTOK   128

// ---------------- scratch (static __device__ globals; zero-init at load) ----
__device__ float g_emb[3][BZ][Dp];          // 0=sh 1=st 2=p, cols >=150 stay 0
__device__ float g_Tt[6][Dp][NT];           // Tt[q][k][i*160+j] = T_q[i][k][j]
__device__ float g_w [6][BZ][NT];           // w[q][bz][i*160+j]
__device__ float g_v [6][BZ][NTOK * Dp];    // v[q][bz][x][j]

// operand selection per triaffine q:
// q0 span_psh: X=sh Y=st Z=p   q1 span_pst: X=sh Y=st Z=p
// q2 ph_sib:   X=sh Y=sh Z=p   q3 pt_sib:   X=st Y=st Z=p
// q4 ph_cop:   X=p  Y=p  Z=sh  q5 pt_cop:   X=p  Y=p  Z=st
__constant__ int c_ZI[6] = {2,2,2,2,0,1};
__constant__ int c_XI[6] = {0,0,0,1,2,2};
__constant__ int c_YI[6] = {1,1,0,1,2,2};

// ---------------- zero the buffers whose padding must be 0 -----------------
__global__ void k_zero()
{
    const size_t nTt  = (size_t)6 * Dp * NT;          // 24.576M floats
    const size_t nEmb = (size_t)3 * BZ * Dp;          // 122880 floats
    float* pT = &g_Tt[0][0][0];
    float* pE = &g_emb[0][0][0];
    size_t stride = (size_t)gridDim.x * blockDim.x;
    for (size_t i = blockIdx.x * (size_t)blockDim.x + threadIdx.x; i < nTt; i += stride)
        pT[i] = 0.f;
    for (size_t i = blockIdx.x * (size_t)blockDim.x + threadIdx.x; i < nEmb; i += stride)
        pE[i] = 0.f;
}

// ---------------- MLP: emb[e][row][c] = leaky(x[row]·W_e + b_e) ------------
__global__ void k_mlp(const float* __restrict__ x,
                      const float* __restrict__ W0, const float* __restrict__ b0,
                      const float* __restrict__ W1, const float* __restrict__ b1,
                      const float* __restrict__ W2, const float* __restrict__ b2)
{
    int row = blockIdx.x;      // 0..255 (= b*128 + token)
    int e   = blockIdx.y;      // 0..2
    const float* W = (e == 0) ? W0 : (e == 1) ? W1 : W2;
    const float* bb = (e == 0) ? b0 : (e == 1) ? b1 : b2;

    __shared__ float xs[DIN];
    int tid = threadIdx.x;     // 0..159
    for (int k = tid; k < DIN; k += 160) xs[k] = x[row * DIN + k];
    __syncthreads();

    if (tid < D) {
        float acc = bb[tid];
        #pragma unroll 8
        for (int k = 0; k < DIN; ++k)
            acc += xs[k] * W[k * D + tid];
        g_emb[e][row][tid] = (acc >= 0.f) ? acc : 0.1f * acc;
    }
}

// ---------------- transpose T[i,k,j] -> Tt[k][i*160+j] ---------------------
__global__ void k_transT(const float* __restrict__ T0, const float* __restrict__ T1,
                         const float* __restrict__ T2, const float* __restrict__ T3,
                         const float* __restrict__ T4, const float* __restrict__ T5)
{
    int k = blockIdx.x, i = blockIdx.y, q = blockIdx.z;
    const float* T = (q==0)?T0:(q==1)?T1:(q==2)?T2:(q==3)?T3:(q==4)?T4:T5;
    int j = threadIdx.x;
    if (j < D)
        g_Tt[q][k][i * Dp + j] = T[(i * D + k) * D + j];
}

// ---------------- stage A: w[q][bz][n] = sum_k Z[bz][k] * Tt[q][k][n] -------
// GEMM M=256 N=25600 K=160, tile 128x128xk32, 256 thr, 8x8 microtile
__global__ void __launch_bounds__(256, 2) k_stageA()
{
    int q  = blockIdx.z;
    int m0 = blockIdx.y * 128;
    int n0 = blockIdx.x * 128;
    const float* Zp = &g_emb[c_ZI[q]][0][0];   // [256][160]
    const float* Bp = &g_Tt[q][0][0];          // [160][25600]
    float*       Cp = &g_w[q][0][0];

    __shared__ float As[32][132];
    __shared__ float Bs[32][132];

    int tid = threadIdx.x;
    int ty = tid >> 4, tx = tid & 15;
    float acc[8][8];
    #pragma unroll
    for (int i = 0; i < 8; ++i)
        #pragma unroll
        for (int j = 0; j < 8; ++j) acc[i][j] = 0.f;

    for (int k0 = 0; k0 < Dp; k0 += 32) {
        {   // As[kc][m] = Z[m0+m][k0+kc]   (transposed load)
            int m = tid >> 1;
            int koff = (tid & 1) * 16;
            const float* src = Zp + (m0 + m) * Dp + k0 + koff;
            #pragma unroll
            for (int c = 0; c < 4; ++c) {
                float4 v = *(const float4*)(src + 4 * c);
                As[koff + 4*c + 0][m] = v.x;
                As[koff + 4*c + 1][m] = v.y;
                As[koff + 4*c + 2][m] = v.z;
                As[koff + 4*c + 3][m] = v.w;
            }
        }
        {   // Bs[kc][n] = Bp[(k0+kc)*NT + n0+n]  (direct, coalesced)
            int kc = tid >> 3;
            int noff = (tid & 7) * 16;
            const float* src = Bp + (size_t)(k0 + kc) * NT + n0 + noff;
            #pragma unroll
            for (int c = 0; c < 4; ++c)
                *(float4*)&Bs[kc][noff + 4*c] = *(const float4*)(src + 4*c);
        }
        __syncthreads();
        #pragma unroll
        for (int kc = 0; kc < 32; ++kc) {
            float4 a0 = *(const float4*)&As[kc][ty * 8];
            float4 a1 = *(const float4*)&As[kc][ty * 8 + 4];
            float4 b0 = *(const float4*)&Bs[kc][tx * 8];
            float4 b1 = *(const float4*)&Bs[kc][tx * 8 + 4];
            float a[8] = {a0.x,a0.y,a0.z,a0.w,a1.x,a1.y,a1.z,a1.w};
            float b[8] = {b0.x,b0.y,b0.z,b0.w,b1.x,b1.y,b1.z,b1.w};
            #pragma unroll
            for (int i = 0; i < 8; ++i)
                #pragma unroll
                for (int j = 0; j < 8; ++j)
                    acc[i][j] += a[i] * b[j];
        }
        __syncthreads();
    }
    #pragma unroll
    for (int i = 0; i < 8; ++i) {
        float* dst = Cp + (size_t)(m0 + ty * 8 + i) * NT + n0 + tx * 8;
        float4 s0 = {acc[i][0],acc[i][1],acc[i][2],acc[i][3]};
        float4 s1 = {acc[i][4],acc[i][5],acc[i][6],acc[i][7]};
        *(float4*)dst       = s0;
        *(float4*)(dst + 4) = s1;
    }
}

// ---------------- stage B: v[q][bz][x][j] = sum_i X[x][i] * w[i*160+j] -----
// GEMM per (q,bz): M=128 N=160 K=160, 256 thr, 8x10 microtile
__global__ void __launch_bounds__(256, 2) k_stageB()
{
    int q  = blockIdx.y;
    int bz = blockIdx.x;
    int b  = bz >> 7;
    const float* Xp = &g_emb[c_XI[q]][b * NTOK][0];  // [128][160]
    const float* Wp = &g_w[q][bz][0];                // [160][160]
    float*       Vp = &g_v[q][bz][0];                // [128][160]

    __shared__ float As[32][132];
    __shared__ float Bs[32][160];

    int tid = threadIdx.x;
    int ty = tid >> 4, tx = tid & 15;
    float acc[8][10];
    #pragma unroll
    for (int i = 0; i < 8; ++i)
        #pragma unroll
        for (int j = 0; j < 10; ++j) acc[i][j] = 0.f;

    for (int k0 = 0; k0 < Dp; k0 += 32) {
        {   // As[kc][m] = X[m][k0+kc]
            int m = tid >> 1;
            int koff = (tid & 1) * 16;
            const float* src = Xp + m * Dp + k0 + koff;
            #pragma unroll
            for (int c = 0; c < 4; ++c) {
                float4 v = *(const float4*)(src + 4 * c);
                As[koff + 4*c + 0][m] = v.x;
                As[koff + 4*c + 1][m] = v.y;
                As[koff + 4*c + 2][m] = v.z;
                As[koff + 4*c + 3][m] = v.w;
            }
        }
        {   // Bs[kc][j] = w[(k0+kc)*160 + j]
            int kc = tid >> 3;
            int joff = (tid & 7) * 20;
            const float* src = Wp + (k0 + kc) * Dp + joff;
            #pragma unroll
            for (int c = 0; c < 5; ++c)
                *(float4*)&Bs[kc][joff + 4*c] = *(const float4*)(src + 4*c);
        }
        __syncthreads();
        #pragma unroll
        for (int kc = 0; kc < 32; ++kc) {
            float4 a0 = *(const float4*)&As[kc][ty * 8];
            float4 a1 = *(const float4*)&As[kc][ty * 8 + 4];
            float a[8] = {a0.x,a0.y,a0.z,a0.w,a1.x,a1.y,a1.z,a1.w};
            float bb[10];
            #pragma unroll
            for (int c = 0; c < 5; ++c) {
                float2 v = *(const float2*)&Bs[kc][tx * 10 + 2 * c];
                bb[2*c] = v.x; bb[2*c+1] = v.y;
            }
            #pragma unroll
            for (int i = 0; i < 8; ++i)
                #pragma unroll
                for (int j = 0; j < 10; ++j)
                    acc[i][j] += a[i] * bb[j];
        }
        __syncthreads();
    }
    #pragma unroll
    for (int i = 0; i < 8; ++i) {
        float* dst = Vp + (ty * 8 + i) * Dp + tx * 10;
        #pragma unroll
        for (int c = 0; c < 5; ++c) {
            float2 s = {acc[i][2*c], acc[i][2*c+1]};
            *(float2*)(dst + 2 * c) = s;
        }
    }
}

// ---------------- stage C: s[x][y] = sum_j v[x][j] * Y[y][j]; sym + write ---
// GEMM per (q,bz): M=N=128 K=160; triu_sym fused via smem mirror exchange
__global__ void __launch_bounds__(256, 2) k_stageC(float* __restrict__ out)
{
    int q  = blockIdx.y;
    int bz = blockIdx.x;
    int b  = bz >> 7, z = bz & 127;
    const float* Ap = &g_v[q][bz][0];                // [128][160] (x, j)
    const float* Yp = &g_emb[c_YI[q]][b * NTOK][0];  // [128][160] (y, j)

    __shared__ float sm[2 * 32 * 132];               // 33792 B
    float (*As)[132] = (float (*)[132])sm;
    float (*Bs)[132] = (float (*)[132])(sm + 32 * 132);

    int tid = threadIdx.x;
    int ty = tid >> 4, tx = tid & 15;
    float acc[8][8];
    #pragma unroll
    for (int i = 0; i < 8; ++i)
        #pragma unroll
        for (int j = 0; j < 8; ++j) acc[i][j] = 0.f;

    for (int k0 = 0; k0 < Dp; k0 += 32) {
        {   // As[kc][x] = v[x][k0+kc]
            int m = tid >> 1;
            int koff = (tid & 1) * 16;
            const float* src = Ap + m * Dp + k0 + koff;
            #pragma unroll
            for (int c = 0; c < 4; ++c) {
                float4 v = *(const float4*)(src + 4 * c);
                As[koff + 4*c + 0][m] = v.x;
                As[koff + 4*c + 1][m] = v.y;
                As[koff + 4*c + 2][m] = v.z;
                As[koff + 4*c + 3][m] = v.w;
            }
        }
        {   // Bs[kc][y] = Y[y][k0+kc]
            int m = tid >> 1;
            int koff = (tid & 1) * 16;
            const float* src = Yp + m * Dp + k0 + koff;
            #pragma unroll
            for (int c = 0; c < 4; ++c) {
                float4 v = *(const float4*)(src + 4 * c);
                Bs[koff + 4*c + 0][m] = v.x;
                Bs[koff + 4*c + 1][m] = v.y;
                Bs[koff + 4*c + 2][m] = v.z;
                Bs[koff + 4*c + 3][m] = v.w;
            }
        }
        __syncthreads();
        #pragma unroll
        for (int kc = 0; kc < 32; ++kc) {
            float4 a0 = *(const float4*)&As[kc][ty * 8];
            float4 a1 = *(const float4*)&As[kc][ty * 8 + 4];
            float4 b0 = *(const float4*)&Bs[kc][tx * 8];
            float4 b1 = *(const float4*)&Bs[kc][tx * 8 + 4];
            float a[8] = {a0.x,a0.y,a0.z,a0.w,a1.x,a1.y,a1.z,a1.w};
            float bv[8] = {b0.x,b0.y,b0.z,b0.w,b1.x,b1.y,b1.z,b1.w};
            #pragma unroll
            for (int i = 0; i < 8; ++i)
                #pragma unroll
                for (int j = 0; j < 8; ++j)
                    acc[i][j] += a[i] * bv[j];
        }
        __syncthreads();
    }

    // Fused triu_sym: res[x][y] = (x<=y) ? s[x][y] : s[y][x]
    float res[8][8];
    if (q == 0) {
        #pragma unroll
        for (int i = 0; i < 8; ++i)
            #pragma unroll
            for (int j = 0; j < 8; ++j) res[i][j] = acc[i][j];
    } else {
        // upper-triangle threads (ty<tx) park tiles in (reused) smem
        if (ty < tx) {
            int u = ty * 15 - (ty * (ty - 1)) / 2 + (tx - ty - 1);   // 0..119
            #pragma unroll
            for (int i = 0; i < 8; ++i)
                #pragma unroll
                for (int j = 0; j < 8; ++j)
                    sm[u * 64 + i * 8 + j] = acc[i][j];
        }
        __syncthreads();
        if (ty < tx) {                      // strictly upper: keep own value
            #pragma unroll
            for (int i = 0; i < 8; ++i)
                #pragma unroll
                for (int j = 0; j < 8; ++j) res[i][j] = acc[i][j];
        } else if (ty == tx) {              // diagonal tile: local mirror
            #pragma unroll
            for (int i = 0; i < 8; ++i)
                #pragma unroll
                for (int j = 0; j < 8; ++j)
                    res[i][j] = (i <= j) ? acc[i][j] : acc[j][i];
        } else {                            // strictly lower: read mirror tile
            int u = tx * 15 - (tx * (tx - 1)) / 2 + (ty - tx - 1);
            #pragma unroll
            for (int i = 0; i < 8; ++i)
                #pragma unroll
                for (int j = 0; j < 8; ++j)
                    res[i][j] = sm[u * 64 + j * 8 + i];
        }
    }

    size_t qbase = (size_t)q * 4194304;     // 2*128^3 per output tensor
    if (q < 4) {
        // out[b][z][x][y]
        float* o = out + qbase + (size_t)bz * 16384;
        #pragma unroll
        for (int i = 0; i < 8; ++i) {
            float* dst = o + (ty * 8 + i) * 128 + tx * 8;
            float4 s0 = {res[i][0],res[i][1],res[i][2],res[i][3]};
            float4 s1 = {res[i][4],res[i][5],res[i][6],res[i][7]};
            *(float4*)dst       = s0;
            *(float4*)(dst + 4) = s1;
        }
    } else {
        // co-parent permute (0,2,3,1): out[b][x][y][z]
        float* o = out + qbase + (size_t)b * 2097152 + z;
        #pragma unroll
        for (int i = 0; i < 8; ++i)
            #pragma unroll
            for (int j = 0; j < 8; ++j)
                o[(size_t)(ty * 8 + i) * 16384 + (tx * 8 + j) * 128] = res[i][j];
    }
}

// ---------------------------------------------------------------------------
extern "C" void kernel_launch(void* const* d_in, const int* in_sizes, int n_in,
                              void* d_out, int out_size)
{
    const float* x      = (const float*)d_in[0];
    const float* W_sh   = (const float*)d_in[1];
    const float* b_sh   = (const float*)d_in[2];
    const float* W_st   = (const float*)d_in[3];
    const float* b_st   = (const float*)d_in[4];
    const float* W_p    = (const float*)d_in[5];
    const float* b_p    = (const float*)d_in[6];
    const float* T_pt   = (const float*)d_in[7];
    const float* T_ph   = (const float*)d_in[8];
    const float* T_phsib= (const float*)d_in[9];
    const float* T_ptsib= (const float*)d_in[10];
    const float* T_phcop= (const float*)d_in[11];
    const float* T_ptcop= (const float*)d_in[12];

    k_zero  <<<1024, 256>>>();
    k_mlp   <<<dim3(BZ, 3), 160>>>(x, W_sh, b_sh, W_st, b_st, W_p, b_p);
    // q order: 0=T_ph 1=T_pt 2=T_phsib 3=T_ptsib 4=T_phcop 5=T_ptcop
    k_transT<<<dim3(D, D, 6), 160>>>(T_ph, T_pt, T_phsib, T_ptsib, T_phcop, T_ptcop);
    k_stageA<<<dim3(200, 2, 6), 256>>>();
    k_stageB<<<dim3(BZ, 6), 256>>>();
    k_stageC<<<dim3(BZ, 6), 256>>>((float*)d_out);
}

// round 4
// speedup vs baseline: 1.7385x; 1.7385x over previous
#include <cuda_runtime.h>
#include <cuda_bf16.h>
#include <cstdint>

#define D      150
#define Dp     160
#define NTOT   25600     // Dp*Dp, n = j*160 + i
#define BZ     256
#define DIN    1024

// ---------------- scratch (__device__ globals; zero-init at load; pads never
// written -> stay zero -> no predication anywhere) -------------------------
__device__ float g_emb[3][BZ][Dp];
__device__ __nv_bfloat16 g_eh[3][BZ][Dp];        // emb hi image (row-major, k-major rows)
__device__ __nv_bfloat16 g_el[3][BZ][Dp];        // emb lo image
__device__ __nv_bfloat16 g_tbh[6][NTOT][Dp];     // T image: [q][n=(j*160+i)][k], hi
__device__ __nv_bfloat16 g_tbl[6][NTOT][Dp];     // lo
__device__ __nv_bfloat16 g_wbh[6][BZ][Dp][Dp];   // w image: [q][bz][j][i] = w[i][j], hi
__device__ __nv_bfloat16 g_wbl[6][BZ][Dp][Dp];   // lo

// q0 span_psh: X=sh Y=st Z=p (T_ph, no sym)   q1 span_pst: X=sh Y=st Z=p (T_pt, sym)
// q2 ph_sib:   X=sh Y=sh Z=p   q3 pt_sib: X=st Y=st Z=p
// q4 ph_cop:   X=p  Y=p  Z=sh  q5 pt_cop: X=p  Y=p  Z=st   (q4,q5 permuted out)
__constant__ int c_ZI[6] = {2,2,2,2,0,1};
__constant__ int c_XI[6] = {0,0,0,1,2,2};
__constant__ int c_YI[6] = {1,1,0,1,2,2};

// ---------------- low-level helpers ----------------------------------------
__device__ __forceinline__ uint32_t smem_u32(const void* p){
    uint32_t a;
    asm("{ .reg .u64 t; cvta.to.shared.u64 t, %1; cvt.u32.u64 %0, t; }" : "=r"(a) : "l"(p));
    return a;
}
__device__ __forceinline__ void split_pack(float a, float b, uint32_t& h, uint32_t& l){
    __nv_bfloat16 ah = __float2bfloat16(a), bh = __float2bfloat16(b);
    __nv_bfloat16 al = __float2bfloat16(a - __bfloat162float(ah));
    __nv_bfloat16 bl = __float2bfloat16(b - __bfloat162float(bh));
    h = (uint32_t)__bfloat16_as_ushort(ah) | ((uint32_t)__bfloat16_as_ushort(bh) << 16);
    l = (uint32_t)__bfloat16_as_ushort(al) | ((uint32_t)__bfloat16_as_ushort(bl) << 16);
}
__device__ __forceinline__ void mma16816(float* c, const uint32_t* a, uint32_t b0, uint32_t b1){
    asm volatile("mma.sync.aligned.m16n8k16.row.col.f32.bf16.bf16.f32 "
        "{%0,%1,%2,%3}, {%4,%5,%6,%7}, {%8,%9}, {%0,%1,%2,%3};"
        : "+f"(c[0]), "+f"(c[1]), "+f"(c[2]), "+f"(c[3])
        : "r"(a[0]), "r"(a[1]), "r"(a[2]), "r"(a[3]), "r"(b0), "r"(b1));
}
__device__ __forceinline__ void ldsm4(uint32_t* r, uint32_t a){
    asm volatile("ldmatrix.sync.aligned.m8n8.x4.shared.b16 {%0,%1,%2,%3}, [%4];"
        : "=r"(r[0]), "=r"(r[1]), "=r"(r[2]), "=r"(r[3]) : "r"(a));
}
__device__ __forceinline__ void cpa16(uint32_t s, const void* g){
    asm volatile("cp.async.cg.shared.global [%0], [%1], 16;" :: "r"(s), "l"(g));
}
#define CP_COMMIT() asm volatile("cp.async.commit_group;" ::: "memory")
#define CP_WAIT1()  asm volatile("cp.async.wait_group 1;" ::: "memory")
#define CP_WAIT0()  asm volatile("cp.async.wait_group 0;" ::: "memory")

// chunk layout: [row][u] u=16B half of 16 bf16 k-slice; XOR swizzle => ldmatrix
// phases hit all 32 banks.  byte = row*32 + ((u ^ (row>>2))&1)*16
__device__ __forceinline__ uint32_t swz(int row, int u){
    return (uint32_t)(row * 32 + (((u ^ (row >> 2)) & 1) << 4));
}
// ldmatrix x4 address for thread `ln`, tile row base r0 (A-frag and B-frag
// share the same pattern: mats = {rows r0..+7 u0, r0+8..+15 u0, r0..+7 u1, r0+8..+15 u1})
__device__ __forceinline__ uint32_t lds_addr(uint32_t base, int r0, int ln){
    int g = ln >> 3, tr = ln & 7;
    int row = r0 + ((g & 1) << 3) + tr;
    return base + swz(row, g >> 1);
}

// ---------------- MLP -------------------------------------------------------
__global__ void k_mlp(const float* __restrict__ x,
                      const float* __restrict__ W0, const float* __restrict__ b0,
                      const float* __restrict__ W1, const float* __restrict__ b1,
                      const float* __restrict__ W2, const float* __restrict__ b2)
{
    int row = blockIdx.x, e = blockIdx.y;
    const float* W  = (e == 0) ? W0 : (e == 1) ? W1 : W2;
    const float* bb = (e == 0) ? b0 : (e == 1) ? b1 : b2;
    __shared__ float xs[DIN];
    int tid = threadIdx.x;
    for (int k = tid; k < DIN; k += 160) xs[k] = x[row * DIN + k];
    __syncthreads();
    if (tid < D) {
        float acc = bb[tid];
        #pragma unroll 8
        for (int k = 0; k < DIN; ++k) acc += xs[k] * W[k * D + tid];
        g_emb[e][row][tid] = (acc >= 0.f) ? acc : 0.1f * acc;
    }
}

// ---------------- emb -> split bf16 images ---------------------------------
__global__ void k_embimg()
{
    int idx = blockIdx.x * 256 + threadIdx.x;      // 3*256*80 = 61440 total
    if (idx >= 3 * 256 * 80) return;
    int e = idx / 20480, rem = idx % 20480;
    int row = rem / 80, kp = rem % 80;
    uint32_t h, l;
    split_pack(g_emb[e][row][2*kp], g_emb[e][row][2*kp+1], h, l);
    *(uint32_t*)&g_eh[e][row][2*kp] = h;
    *(uint32_t*)&g_el[e][row][2*kp] = l;
}

// ---------------- T[i][k][j] -> TB[q][(j*160+i)][k] hi/lo -------------------
__global__ void k_timg(const float* __restrict__ T0, const float* __restrict__ T1,
                       const float* __restrict__ T2, const float* __restrict__ T3,
                       const float* __restrict__ T4, const float* __restrict__ T5)
{
    int q = blockIdx.z, i = blockIdx.y, j0 = blockIdx.x * 32;
    const float* T = (q==0)?T0:(q==1)?T1:(q==2)?T2:(q==3)?T3:(q==4)?T4:T5;
    __shared__ float ts[32][152];
    int tid = threadIdx.x;
    for (int t = tid; t < 150 * 32; t += 256) {
        int k = t >> 5, j = t & 31;
        if (j0 + j < D) ts[j][k] = T[(i * D + k) * D + j0 + j];
    }
    __syncthreads();
    for (int t = tid; t < 32 * 75; t += 256) {
        int j = t / 75, kp = t % 75;
        if (j0 + j < D) {
            uint32_t h, l;
            split_pack(ts[j][2*kp], ts[j][2*kp+1], h, l);
            int n = (j0 + j) * Dp + i;
            *(uint32_t*)&g_tbh[q][n][2*kp] = h;
            *(uint32_t*)&g_tbl[q][n][2*kp] = l;
        }
    }
}

// ---------------- stage A (mma): w = Z . TB^T, epilogue -> wB images --------
// M=256, N=25600, K=160.  Tile 128x128, warp tile 32x64 (warps 4m x 2n).
__device__ __forceinline__ void prefA(uint32_t sb, int buf, int k0, int tid,
    const __nv_bfloat16* Zh, const __nv_bfloat16* Zl,
    const __nv_bfloat16* Bh, const __nv_bfloat16* Bl, int m0, int n0)
{
    #pragma unroll
    for (int t3 = 0; t3 < 4; ++t3) {
        int t = tid + t3 * 256;
        int arr = t >> 8, rr = (t >> 1) & 127, u = t & 1;
        uint32_t dst = sb + buf * 16384 + arr * 4096 + swz(rr, u);
        const __nv_bfloat16* g;
        if (arr == 0)      g = Zh + (size_t)(m0 + rr) * Dp + k0 + u * 8;
        else if (arr == 1) g = Zl + (size_t)(m0 + rr) * Dp + k0 + u * 8;
        else if (arr == 2) g = Bh + (size_t)(n0 + rr) * Dp + k0 + u * 8;
        else               g = Bl + (size_t)(n0 + rr) * Dp + k0 + u * 8;
        cpa16(dst, g);
    }
    CP_COMMIT();
}

__global__ void __launch_bounds__(256, 2) k_stageA()
{
    int q = blockIdx.z, m0 = blockIdx.y * 128, n0 = blockIdx.x * 128;
    int tid = threadIdx.x, w = tid >> 5, ln = tid & 31;
    int wm = w & 3, wn = w >> 2;
    __shared__ __align__(16) unsigned char smb[2][16384];
    uint32_t sb = smem_u32(smb);
    int zi = c_ZI[q];
    const __nv_bfloat16 *Zh = &g_eh[zi][0][0], *Zl = &g_el[zi][0][0];
    const __nv_bfloat16 *Bh = &g_tbh[q][0][0], *Bl = &g_tbl[q][0][0];

    float acc[2][8][4];
    #pragma unroll
    for (int a = 0; a < 2; ++a)
        #pragma unroll
        for (int b = 0; b < 8; ++b)
            #pragma unroll
            for (int c = 0; c < 4; ++c) acc[a][b][c] = 0.f;

    prefA(sb, 0, 0, tid, Zh, Zl, Bh, Bl, m0, n0);
    for (int ks = 0; ks < 10; ++ks) {
        if (ks < 9) { prefA(sb, (ks + 1) & 1, (ks + 1) * 16, tid, Zh, Zl, Bh, Bl, m0, n0); CP_WAIT1(); }
        else CP_WAIT0();
        __syncthreads();
        uint32_t base = sb + (ks & 1) * 16384;
        uint32_t ah[2][4], al[2][4];
        #pragma unroll
        for (int mt = 0; mt < 2; ++mt) {
            ldsm4(ah[mt], lds_addr(base,        wm * 32 + mt * 16, ln));
            ldsm4(al[mt], lds_addr(base + 4096, wm * 32 + mt * 16, ln));
        }
        #pragma unroll
        for (int p = 0; p < 4; ++p) {
            uint32_t bh[4], bl[4];
            ldsm4(bh, lds_addr(base + 8192,  wn * 64 + p * 16, ln));
            ldsm4(bl, lds_addr(base + 12288, wn * 64 + p * 16, ln));
            #pragma unroll
            for (int mt = 0; mt < 2; ++mt) {
                mma16816(acc[mt][2*p],   ah[mt], bh[0], bh[2]);
                mma16816(acc[mt][2*p],   ah[mt], bl[0], bl[2]);
                mma16816(acc[mt][2*p],   al[mt], bh[0], bh[2]);
                mma16816(acc[mt][2*p+1], ah[mt], bh[1], bh[3]);
                mma16816(acc[mt][2*p+1], ah[mt], bl[1], bl[3]);
                mma16816(acc[mt][2*p+1], al[mt], bh[1], bh[3]);
            }
        }
        __syncthreads();
    }

    // epilogue: c-frag (m, n): n -> (j,i); store wB[q][m][j][i] hi/lo (i even pair)
    __nv_bfloat16* WH = &g_wbh[0][0][0][0];
    __nv_bfloat16* WL = &g_wbl[0][0][0][0];
    int yb = 2 * (ln & 3);
    #pragma unroll
    for (int mt = 0; mt < 2; ++mt) {
        int mA = m0 + wm * 32 + mt * 16 + (ln >> 2);
        #pragma unroll
        for (int nt = 0; nt < 8; ++nt) {
            int n = n0 + wn * 64 + nt * 8 + yb;
            int j = n / 160, i = n - j * 160;
            size_t off0 = ((size_t)(q * BZ + mA)) * 25600 + j * 160 + i;
            size_t off1 = off0 + (size_t)8 * 25600;
            uint32_t h, l;
            split_pack(acc[mt][nt][0], acc[mt][nt][1], h, l);
            *(uint32_t*)(WH + off0) = h; *(uint32_t*)(WL + off0) = l;
            split_pack(acc[mt][nt][2], acc[mt][nt][3], h, l);
            *(uint32_t*)(WH + off1) = h; *(uint32_t*)(WL + off1) = l;
        }
    }
}

// ---------------- fused B+C per (q,bz) --------------------------------------
// stage B: v[x][j] = sum_i X[x][i] wB[j][i]  (M=128,N=160,K=160), warp tile 16x160
// stage C: s[x][y] = sum_j v[x][j] Y[y][j]   (A-frags repacked from B's C-frags)
__device__ __forceinline__ void prefB(uint32_t sb, int buf, int k0, int tid,
    const __nv_bfloat16* Xh, const __nv_bfloat16* Xl,
    const __nv_bfloat16* Wh, const __nv_bfloat16* Wl)
{
    for (int t = tid; t < 1152; t += 256) {
        uint32_t dst; const __nv_bfloat16* g;
        if (t < 512) {
            int img = t >> 8, rr = (t >> 1) & 127, u = t & 1;
            dst = sb + buf * 18432 + img * 4096 + swz(rr, u);
            g = (img ? Xl : Xh) + (size_t)rr * Dp + k0 + u * 8;
        } else {
            int t2 = t - 512;
            int img = t2 / 320, r2 = t2 - img * 320;
            int rr = r2 >> 1, u = r2 & 1;
            dst = sb + buf * 18432 + 8192 + img * 5120 + swz(rr, u);
            g = (img ? Wl : Wh) + (size_t)rr * Dp + k0 + u * 8;
        }
        cpa16(dst, g);
    }
    CP_COMMIT();
}
__device__ __forceinline__ void prefC(uint32_t sb, int buf, int k0, int tid,
    const __nv_bfloat16* Yh, const __nv_bfloat16* Yl)
{
    for (int t = tid; t < 512; t += 256) {
        int img = t >> 8, rr = (t >> 1) & 127, u = t & 1;
        uint32_t dst = sb + buf * 18432 + img * 4096 + swz(rr, u);
        const __nv_bfloat16* g = (img ? Yl : Yh) + (size_t)rr * Dp + k0 + u * 8;
        cpa16(dst, g);
    }
    CP_COMMIT();
}
__device__ __forceinline__ void sym_store(float* o, int x, int y, float v, int sx, int sy){
    if (x <= y) {
        o[(size_t)x * sx + (size_t)y * sy] = v;
        if (x < y) o[(size_t)y * sx + (size_t)x * sy] = v;
    }
}

__global__ void __launch_bounds__(256, 1) k_fusedBC(float* __restrict__ out)
{
    int q = blockIdx.y, bz = blockIdx.x, b = bz >> 7, z = bz & 127;
    int tid = threadIdx.x, w = tid >> 5, ln = tid & 31;
    __shared__ __align__(16) unsigned char smb[2][18432];
    uint32_t sb = smem_u32(smb);

    const __nv_bfloat16 *Xh = &g_eh[c_XI[q]][b*128][0], *Xl = &g_el[c_XI[q]][b*128][0];
    const __nv_bfloat16 *Wh = &g_wbh[q][bz][0][0],      *Wl = &g_wbl[q][bz][0][0];
    const __nv_bfloat16 *Yh = &g_eh[c_YI[q]][b*128][0], *Yl = &g_el[c_YI[q]][b*128][0];

    // ---- stage B
    float accB[20][4];
    #pragma unroll
    for (int i = 0; i < 20; ++i)
        #pragma unroll
        for (int c = 0; c < 4; ++c) accB[i][c] = 0.f;

    prefB(sb, 0, 0, tid, Xh, Xl, Wh, Wl);
    for (int ks = 0; ks < 10; ++ks) {
        if (ks < 9) { prefB(sb, (ks + 1) & 1, (ks + 1) * 16, tid, Xh, Xl, Wh, Wl); CP_WAIT1(); }
        else CP_WAIT0();
        __syncthreads();
        uint32_t base = sb + (ks & 1) * 18432;
        uint32_t ah[4], al[4];
        ldsm4(ah, lds_addr(base,        w * 16, ln));
        ldsm4(al, lds_addr(base + 4096, w * 16, ln));
        #pragma unroll
        for (int p = 0; p < 10; ++p) {
            uint32_t bh[4], bl[4];
            ldsm4(bh, lds_addr(base + 8192,  p * 16, ln));
            ldsm4(bl, lds_addr(base + 13312, p * 16, ln));
            mma16816(accB[2*p],   ah, bh[0], bh[2]);
            mma16816(accB[2*p],   ah, bl[0], bl[2]);
            mma16816(accB[2*p],   al, bh[0], bh[2]);
            mma16816(accB[2*p+1], ah, bh[1], bh[3]);
            mma16816(accB[2*p+1], ah, bl[1], bl[3]);
            mma16816(accB[2*p+1], al, bh[1], bh[3]);
        }
        __syncthreads();
    }

    // prefetch stage C chunk 0 while repacking (buffers free, groups drained)
    prefC(sb, 0, 0, tid, Yh, Yl);

    // ---- repack: stage B C-frags -> stage C A-frags (registers only)
    uint32_t a2h[10][4], a2l[10][4];
    #pragma unroll
    for (int kt = 0; kt < 10; ++kt) {
        split_pack(accB[2*kt][0],   accB[2*kt][1],   a2h[kt][0], a2l[kt][0]);
        split_pack(accB[2*kt][2],   accB[2*kt][3],   a2h[kt][1], a2l[kt][1]);
        split_pack(accB[2*kt+1][0], accB[2*kt+1][1], a2h[kt][2], a2l[kt][2]);
        split_pack(accB[2*kt+1][2], accB[2*kt+1][3], a2h[kt][3], a2l[kt][3]);
    }

    // ---- stage C
    float accC[16][4];
    #pragma unroll
    for (int i = 0; i < 16; ++i)
        #pragma unroll
        for (int c = 0; c < 4; ++c) accC[i][c] = 0.f;

    #pragma unroll
    for (int ks = 0; ks < 10; ++ks) {
        if (ks < 9) { prefC(sb, (ks + 1) & 1, (ks + 1) * 16, tid, Yh, Yl); CP_WAIT1(); }
        else CP_WAIT0();
        __syncthreads();
        uint32_t base = sb + (ks & 1) * 18432;
        #pragma unroll
        for (int p = 0; p < 8; ++p) {
            uint32_t bh[4], bl[4];
            ldsm4(bh, lds_addr(base,        p * 16, ln));
            ldsm4(bl, lds_addr(base + 4096, p * 16, ln));
            mma16816(accC[2*p],   a2h[ks], bh[0], bh[2]);
            mma16816(accC[2*p],   a2h[ks], bl[0], bl[2]);
            mma16816(accC[2*p],   a2l[ks], bh[0], bh[2]);
            mma16816(accC[2*p+1], a2h[ks], bh[1], bh[3]);
            mma16816(accC[2*p+1], a2h[ks], bl[1], bl[3]);
            mma16816(accC[2*p+1], a2l[ks], bh[1], bh[3]);
        }
        __syncthreads();
    }

    // ---- epilogue: triu_sym via dual-write; q>=4 permuted strides
    int x0 = w * 16 + (ln >> 2);
    int yb = 2 * (ln & 3);
    if (q == 0) {
        float* o = out + (size_t)bz * 16384;
        #pragma unroll
        for (int nt = 0; nt < 16; ++nt) {
            int y = nt * 8 + yb;
            float2 v0 = {accC[nt][0], accC[nt][1]};
            float2 v1 = {accC[nt][2], accC[nt][3]};
            *(float2*)(o + (size_t)x0 * 128 + y)       = v0;
            *(float2*)(o + (size_t)(x0 + 8) * 128 + y) = v1;
        }
    } else {
        float* o; int sx, sy;
        if (q < 4) { o = out + (size_t)q * 4194304 + (size_t)bz * 16384; sx = 128;   sy = 1;   }
        else       { o = out + (size_t)q * 4194304 + (size_t)b * 2097152 + z; sx = 16384; sy = 128; }
        #pragma unroll
        for (int nt = 0; nt < 16; ++nt) {
            int y = nt * 8 + yb;
            sym_store(o, x0,     y,     accC[nt][0], sx, sy);
            sym_store(o, x0,     y + 1, accC[nt][1], sx, sy);
            sym_store(o, x0 + 8, y,     accC[nt][2], sx, sy);
            sym_store(o, x0 + 8, y + 1, accC[nt][3], sx, sy);
        }
    }
}

// ---------------------------------------------------------------------------
extern "C" void kernel_launch(void* const* d_in, const int* in_sizes, int n_in,
                              void* d_out, int out_size)
{
    const float* x      = (const float*)d_in[0];
    const float* W_sh   = (const float*)d_in[1];
    const float* b_sh   = (const float*)d_in[2];
    const float* W_st   = (const float*)d_in[3];
    const float* b_st   = (const float*)d_in[4];
    const float* W_p    = (const float*)d_in[5];
    const float* b_p    = (const float*)d_in[6];
    const float* T_pt   = (const float*)d_in[7];
    const float* T_ph   = (const float*)d_in[8];
    const float* T_phsib= (const float*)d_in[9];
    const float* T_ptsib= (const float*)d_in[10];
    const float* T_phcop= (const float*)d_in[11];
    const float* T_ptcop= (const float*)d_in[12];

    k_mlp   <<<dim3(BZ, 3), 160>>>(x, W_sh, b_sh, W_st, b_st, W_p, b_p);
    k_embimg<<<240, 256>>>();
    // q order: 0=T_ph 1=T_pt 2=T_phsib 3=T_ptsib 4=T_phcop 5=T_ptcop
    k_timg  <<<dim3(5, D, 6), 256>>>(T_ph, T_pt, T_phsib, T_ptsib, T_phcop, T_ptcop);
    k_stageA<<<dim3(200, 2, 6), 256>>>();
    k_fusedBC<<<dim3(BZ, 6), 256>>>((float*)d_out);
}